// round 1
// baseline (speedup 1.0000x reference)
#include <cuda_runtime.h>

static constexpr int T  = 256;
static constexpr int F  = 16;
static constexpr int U1 = 24;
static constexpr int U2 = 48;
#define LN_EPS 1e-3f
#define FULLMASK 0xffffffffu

// ---------- packed f32x2 helpers ----------
__device__ __forceinline__ unsigned long long pk2(float lo, float hi) {
    unsigned long long r;
    asm("mov.b64 %0, {%1, %2};" : "=l"(r) : "f"(lo), "f"(hi));
    return r;
}
__device__ __forceinline__ unsigned long long dup2(float v) { return pk2(v, v); }
__device__ __forceinline__ float2 un2(unsigned long long p) {
    float2 r;
    asm("mov.b64 {%0, %1}, %2;" : "=f"(r.x), "=f"(r.y) : "l"(p));
    return r;
}
__device__ __forceinline__ unsigned long long ffma2(unsigned long long a,
                                                    unsigned long long b,
                                                    unsigned long long c) {
    unsigned long long d;
    asm("fma.rn.f32x2 %0, %1, %2, %3;" : "=l"(d) : "l"(a), "l"(b), "l"(c));
    return d;
}
__device__ __forceinline__ unsigned long long fadd2(unsigned long long a,
                                                    unsigned long long b) {
    unsigned long long d;
    asm("add.rn.f32x2 %0, %1, %2;" : "=l"(d) : "l"(a), "l"(b));
    return d;
}

// accurate-enough tanh: rel err ~1e-6 (EX2 + RCP based), no branches
__device__ __forceinline__ float tanh_acc(float v) {
    float a = fabsf(v);
    float e = __expf(-2.0f * a);
    float r = __fdividef(1.0f - e, 1.0f + e);
    return copysignf(r, v);
}

__global__ __launch_bounds__(128, 2)
void rnn_scan_kernel(const float* __restrict__ seq,
                     const float* __restrict__ W1,  const float* __restrict__ b1,
                     const float* __restrict__ Wr1, const float* __restrict__ br1,
                     const float* __restrict__ g1,  const float* __restrict__ be1,
                     const float* __restrict__ W2,  const float* __restrict__ b2,
                     const float* __restrict__ Wr2, const float* __restrict__ br2,
                     const float* __restrict__ g2,  const float* __restrict__ be2,
                     const float* __restrict__ Wout, const float* __restrict__ bout,
                     float* __restrict__ out)
{
    __shared__ __align__(16) float sW1[F * U1];     // [16][24]
    __shared__ __align__(16) float sWr1[U1 * U1];   // [24][24]
    __shared__ __align__(16) float sW2g[U1 * U2];   // g1-folded W2 [24][48]
    __shared__ __align__(16) float sWr2[U2 * U2];   // [48][48]
    __shared__ __align__(16) float sC[U2];          // column sums of sW2g
    __shared__ __align__(16) float sb2f[U2];        // b2 + be1 @ W2
    __shared__ float sb1[U1], sbr1[U1], sg1t[U1], sbe1t[U1];
    __shared__ float sbr2[U2], sb2t[U2];
    __shared__ float sg2[U2], sbe2[U2], sWo[U2];
    __shared__ float sbo;

    const int tid = threadIdx.x;

    for (int i = tid; i < F * U1;  i += 128) sW1[i]  = W1[i];
    for (int i = tid; i < U1 * U1; i += 128) sWr1[i] = Wr1[i];
    for (int i = tid; i < U1 * U2; i += 128) sW2g[i] = W2[i];   // raw, folded below
    for (int i = tid; i < U2 * U2; i += 128) sWr2[i] = Wr2[i];
    if (tid < U1) { sb1[tid] = b1[tid]; sbr1[tid] = br1[tid];
                    sg1t[tid] = g1[tid]; sbe1t[tid] = be1[tid]; }
    if (tid < U2) { sbr2[tid] = br2[tid]; sb2t[tid] = b2[tid];
                    sg2[tid] = g2[tid];   sbe2[tid] = be2[tid]; sWo[tid] = Wout[tid]; }
    if (tid == 0) sbo = bout[0];
    __syncthreads();

    // Fold LayerNorm-1 affine into W2:  y = rstd*(nf@W2g - mu*C) + (b2 + be1@W2) + s2
    if (tid < U2) {
        float cs = 0.f, bb = sb2t[tid];
        #pragma unroll
        for (int k = 0; k < U1; ++k) {
            float w0 = sW2g[k * U2 + tid];
            bb = fmaf(sbe1t[k], w0, bb);
            float w = sg1t[k] * w0;
            sW2g[k * U2 + tid] = w;
            cs += w;
        }
        sC[tid] = cs; sb2f[tid] = bb;
    }
    __syncthreads();

    const int g   = tid & 3;                       // lane within 4-lane row group
    const int row = blockIdx.x * 32 + (tid >> 2);  // one batch row per group

    // Precompute packed per-lane bias constants
    unsigned long long b1p[3], br1p[3], br2p[6], b2fp[6], Cp[6];
    #pragma unroll
    for (int p = 0; p < 3; ++p) {
        b1p[p]  = pk2(sb1[6 * g + 2 * p],  sb1[6 * g + 2 * p + 1]);
        br1p[p] = pk2(sbr1[6 * g + 2 * p], sbr1[6 * g + 2 * p + 1]);
    }
    #pragma unroll
    for (int p = 0; p < 6; ++p) {
        br2p[p] = pk2(sbr2[12 * g + 2 * p], sbr2[12 * g + 2 * p + 1]);
        b2fp[p] = pk2(sb2f[12 * g + 2 * p], sb2f[12 * g + 2 * p + 1]);
        Cp[p]   = pk2(sC[12 * g + 2 * p],   sC[12 * g + 2 * p + 1]);
    }

    const float4* sp = reinterpret_cast<const float4*>(seq + (size_t)row * (T * F));
    float4 c0 = sp[0], c1 = sp[1], c2 = sp[2], c3 = sp[3];   // input @ t=0

    unsigned long long s1p[3] = {0ull, 0ull, 0ull};
    unsigned long long s2p[6] = {0ull, 0ull, 0ull, 0ull, 0ull, 0ull};
    float n1[6], n2[12];

    for (int t = 0; t < T; ++t) {
        // prefetch next step's input (distance = whole step body)
        const int tn = (t < T - 1) ? (t + 1) : t;
        float4 nx0 = sp[tn * 4 + 0], nx1 = sp[tn * 4 + 1];
        float4 nx2 = sp[tn * 4 + 2], nx3 = sp[tn * 4 + 3];

        float in[16] = {c0.x, c0.y, c0.z, c0.w, c1.x, c1.y, c1.z, c1.w,
                        c2.x, c2.y, c2.z, c2.w, c3.x, c3.y, c3.z, c3.w};

        // ---- layer1 input matvec:  x = inp@W1 + b1 + s1  (own 6 units) ----
        unsigned long long a1[3];
        #pragma unroll
        for (int p = 0; p < 3; ++p) a1[p] = fadd2(s1p[p], b1p[p]);
        #pragma unroll
        for (int k = 0; k < F; ++k) {
            unsigned long long ik = dup2(in[k]);
            const unsigned long long* w =
                reinterpret_cast<const unsigned long long*>(&sW1[k * U1 + 6 * g]);
            a1[0] = ffma2(ik, w[0], a1[0]);
            a1[1] = ffma2(ik, w[1], a1[1]);
            a1[2] = ffma2(ik, w[2], a1[2]);
        }

        // ---- exchange x across the 4 lanes ----
        float xo[6];
        { float2 u;
          u = un2(a1[0]); xo[0] = u.x; xo[1] = u.y;
          u = un2(a1[1]); xo[2] = u.x; xo[3] = u.y;
          u = un2(a1[2]); xo[4] = u.x; xo[5] = u.y; }
        float xf[24];
        #pragma unroll
        for (int gg = 0; gg < 4; ++gg)
            #pragma unroll
            for (int i = 0; i < 6; ++i)
                xf[gg * 6 + i] = __shfl_sync(FULLMASK, xo[i], gg, 4);

        // ---- layer1 recurrent:  ns1 = tanh(x@Wr1 + br1) ----
        unsigned long long a2[3] = {br1p[0], br1p[1], br1p[2]};
        #pragma unroll
        for (int k = 0; k < U1; ++k) {
            unsigned long long xk = dup2(xf[k]);
            const unsigned long long* w =
                reinterpret_cast<const unsigned long long*>(&sWr1[k * U1 + 6 * g]);
            a2[0] = ffma2(xk, w[0], a2[0]);
            a2[1] = ffma2(xk, w[1], a2[1]);
            a2[2] = ffma2(xk, w[2], a2[2]);
        }
        { float2 u;
          u = un2(a2[0]); n1[0] = tanh_acc(u.x); n1[1] = tanh_acc(u.y);
          u = un2(a2[1]); n1[2] = tanh_acc(u.x); n1[3] = tanh_acc(u.y);
          u = un2(a2[2]); n1[4] = tanh_acc(u.x); n1[5] = tanh_acc(u.y); }

        // ---- exchange ns1 + LN stats on the fly ----
        float nf[24];
        float sm = 0.f, sq = 0.f;
        #pragma unroll
        for (int gg = 0; gg < 4; ++gg)
            #pragma unroll
            for (int i = 0; i < 6; ++i) {
                float v = __shfl_sync(FULLMASK, n1[i], gg, 4);
                nf[gg * 6 + i] = v;
                sm += v;
                sq = fmaf(v, v, sq);
            }
        float mu   = sm * (1.0f / 24.0f);
        float var  = fmaf(-mu, mu, sq * (1.0f / 24.0f));
        float rstd = rsqrtf(var + LN_EPS);

        // ---- layer2 input matvec over raw ns1 (LN folded):  own 12 units ----
        unsigned long long a3[6] = {0ull, 0ull, 0ull, 0ull, 0ull, 0ull};
        #pragma unroll
        for (int k = 0; k < U1; ++k) {
            unsigned long long nk = dup2(nf[k]);
            const ulonglong2* w =
                reinterpret_cast<const ulonglong2*>(&sW2g[k * U2 + 12 * g]);
            ulonglong2 w0 = w[0], w1 = w[1], w2 = w[2];
            a3[0] = ffma2(nk, w0.x, a3[0]); a3[1] = ffma2(nk, w0.y, a3[1]);
            a3[2] = ffma2(nk, w1.x, a3[2]); a3[3] = ffma2(nk, w1.y, a3[3]);
            a3[4] = ffma2(nk, w2.x, a3[4]); a3[5] = ffma2(nk, w2.y, a3[5]);
        }
        unsigned long long mun = dup2(-mu), rsd = dup2(rstd);
        #pragma unroll
        for (int p = 0; p < 6; ++p) {
            unsigned long long tmp = ffma2(mun, Cp[p], a3[p]);
            a3[p] = ffma2(rsd, tmp, fadd2(b2fp[p], s2p[p]));
        }

        // ---- exchange y ----
        float yo[12];
        { float2 u;
          u = un2(a3[0]); yo[0]  = u.x; yo[1]  = u.y;
          u = un2(a3[1]); yo[2]  = u.x; yo[3]  = u.y;
          u = un2(a3[2]); yo[4]  = u.x; yo[5]  = u.y;
          u = un2(a3[3]); yo[6]  = u.x; yo[7]  = u.y;
          u = un2(a3[4]); yo[8]  = u.x; yo[9]  = u.y;
          u = un2(a3[5]); yo[10] = u.x; yo[11] = u.y; }
        float yf[48];
        #pragma unroll
        for (int gg = 0; gg < 4; ++gg)
            #pragma unroll
            for (int i = 0; i < 12; ++i)
                yf[gg * 12 + i] = __shfl_sync(FULLMASK, yo[i], gg, 4);

        // ---- layer2 recurrent:  ns2 = tanh(y@Wr2 + br2) ----
        unsigned long long a4[6] = {br2p[0], br2p[1], br2p[2], br2p[3], br2p[4], br2p[5]};
        #pragma unroll
        for (int k = 0; k < U2; ++k) {
            unsigned long long yk = dup2(yf[k]);
            const ulonglong2* w =
                reinterpret_cast<const ulonglong2*>(&sWr2[k * U2 + 12 * g]);
            ulonglong2 w0 = w[0], w1 = w[1], w2 = w[2];
            a4[0] = ffma2(yk, w0.x, a4[0]); a4[1] = ffma2(yk, w0.y, a4[1]);
            a4[2] = ffma2(yk, w1.x, a4[2]); a4[3] = ffma2(yk, w1.y, a4[3]);
            a4[4] = ffma2(yk, w2.x, a4[4]); a4[5] = ffma2(yk, w2.y, a4[5]);
        }
        { float2 u;
          u = un2(a4[0]); n2[0]  = tanh_acc(u.x); n2[1]  = tanh_acc(u.y);
          u = un2(a4[1]); n2[2]  = tanh_acc(u.x); n2[3]  = tanh_acc(u.y);
          u = un2(a4[2]); n2[4]  = tanh_acc(u.x); n2[5]  = tanh_acc(u.y);
          u = un2(a4[3]); n2[6]  = tanh_acc(u.x); n2[7]  = tanh_acc(u.y);
          u = un2(a4[4]); n2[8]  = tanh_acc(u.x); n2[9]  = tanh_acc(u.y);
          u = un2(a4[5]); n2[10] = tanh_acc(u.x); n2[11] = tanh_acc(u.y); }

        // ---- carry updates ----
        s1p[0] = pk2(n1[0], n1[1]); s1p[1] = pk2(n1[2], n1[3]); s1p[2] = pk2(n1[4], n1[5]);
        #pragma unroll
        for (int p = 0; p < 6; ++p) s2p[p] = pk2(n2[2 * p], n2[2 * p + 1]);

        c0 = nx0; c1 = nx1; c2 = nx2; c3 = nx3;
    }

    // ---- epilogue: LN(s2_final; g2, be2) @ Wout + bout -> sigmoid ----
    float sm = 0.f, sq = 0.f;
    #pragma unroll
    for (int i = 0; i < 12; ++i) { sm += n2[i]; sq = fmaf(n2[i], n2[i], sq); }
    sm += __shfl_xor_sync(FULLMASK, sm, 1, 4);
    sm += __shfl_xor_sync(FULLMASK, sm, 2, 4);
    sq += __shfl_xor_sync(FULLMASK, sq, 1, 4);
    sq += __shfl_xor_sync(FULLMASK, sq, 2, 4);
    float mu   = sm * (1.0f / 48.0f);
    float var  = fmaf(-mu, mu, sq * (1.0f / 48.0f));
    float rstd = rsqrtf(var + LN_EPS);
    float d = 0.f;
    #pragma unroll
    for (int i = 0; i < 12; ++i) {
        int j = 12 * g + i;
        float h = fmaf((n2[i] - mu) * rstd, sg2[j], sbe2[j]);
        d = fmaf(h, sWo[j], d);
    }
    d += __shfl_xor_sync(FULLMASK, d, 1, 4);
    d += __shfl_xor_sync(FULLMASK, d, 2, 4);
    if (g == 0) {
        float z = d + sbo;
        out[row] = __fdividef(1.0f, 1.0f + __expf(-z));
    }
}

extern "C" void kernel_launch(void* const* d_in, const int* in_sizes, int n_in,
                              void* d_out, int out_size)
{
    const float* seq  = (const float*)d_in[0];
    const float* W1   = (const float*)d_in[1];
    const float* b1   = (const float*)d_in[2];
    const float* Wr1  = (const float*)d_in[3];
    const float* br1  = (const float*)d_in[4];
    const float* g1   = (const float*)d_in[5];
    const float* be1  = (const float*)d_in[6];
    const float* W2   = (const float*)d_in[7];
    const float* b2   = (const float*)d_in[8];
    const float* Wr2  = (const float*)d_in[9];
    const float* br2  = (const float*)d_in[10];
    const float* g2   = (const float*)d_in[11];
    const float* be2  = (const float*)d_in[12];
    const float* Wout = (const float*)d_in[13];
    const float* bout = (const float*)d_in[14];

    const int B = in_sizes[0] / (T * F);     // 8192
    dim3 grid(B / 32), block(128);           // 32 rows/CTA, 4 lanes/row
    rnn_scan_kernel<<<grid, block>>>(seq, W1, b1, Wr1, br1, g1, be1,
                                     W2, b2, Wr2, br2, g2, be2, Wout, bout,
                                     (float*)d_out);
}